// round 7
// baseline (speedup 1.0000x reference)
#include <cuda_runtime.h>
#include <cstdint>

// ---------------- problem constants ----------------
#define N_ROWS 16384
#define D_DIM  32

// ---------------- GEMM tiling ----------------
#define TM      256                 // M rows per CTA
#define KB      32                  // K floats per stage (128 B per row)
#define NSTAGE  (N_ROWS / KB)       // 512
#define STAGES  6                   // smem ring buffers
#define QUAD    4                   // stages consumed per sync pair
#define NTHR    512                 // 16 warps: 8 m-warps (m=32) x 2 stage-parity groups

#define A_FLOATS (TM * KB)          // 8192 (unpadded, SW128-swizzled)
#define B_FLOATS 1024               // 32x32 fragment-major, flat
#define A_BYTES (A_FLOATS * 4)      // 32768
#define B_BYTES (B_FLOATS * 4)      // 4096
#define STAGE_FLOATS (A_FLOATS + B_FLOATS)
#define SMEM_TOTAL (STAGES * (A_BYTES + B_BYTES))   // 221184

// scratch (device globals: no allocation allowed anywhere)
// g_hB fragment-major: float idx = ((s*8 + kk*2 + p)*32 + (g*4 + t))*4 + nt
//   holds tf32(h[k][c]), k = s*32 + kk*8 + t + 4p, c = nt*8 + g
__device__ __align__(256) float g_hB[D_DIM * N_ROWS];
__device__ __align__(256) float g_h [N_ROWS * D_DIM];   // h[i][c], fp32 self term

// ---------------- helpers ----------------
__device__ __forceinline__ uint32_t smem_u32(const void* p) {
    uint32_t a;
    asm("{ .reg .u64 t; cvta.to.shared.u64 t, %1; cvt.u32.u64 %0, t; }"
        : "=r"(a) : "l"(p));
    return a;
}

__device__ __forceinline__ void cp16(uint32_t dst, const void* src) {
    asm volatile("cp.async.cg.shared.global [%0], [%1], 16;"
                 :: "r"(dst), "l"(src) : "memory");
}

__device__ __forceinline__ uint32_t f2tf32(float f) {
    uint32_t u;
    asm("cvt.rna.tf32.f32 %0, %1;" : "=r"(u) : "f"(f));
    return u;
}

// m16n8k8 tf32 mma: D += A*B (row-major A, col-major B, fp32 acc)
__device__ __forceinline__ void mma_tf32(float* c,
                                         uint32_t a0, uint32_t a1, uint32_t a2, uint32_t a3,
                                         uint32_t b0, uint32_t b1) {
    asm volatile(
        "mma.sync.aligned.m16n8k8.row.col.f32.tf32.tf32.f32 "
        "{%0,%1,%2,%3}, {%4,%5,%6,%7}, {%8,%9}, {%0,%1,%2,%3};"
        : "+f"(c[0]), "+f"(c[1]), "+f"(c[2]), "+f"(c[3])
        : "r"(a0), "r"(a1), "r"(a2), "r"(a3), "r"(b0), "r"(b1));
}

// fill one K-stage (A: 256 rows x 128B, SW128-swizzled; B: 4KB flat) into slot b
__device__ __forceinline__ void fill_stage(const float* __restrict__ edges,
                                           int m0, int s, int b,
                                           uint32_t sb, int tid) {
    const size_t k0b = (size_t)s * (KB * 4);
    const char* baseA = (const char*)edges + (size_t)m0 * 65536 + k0b;
    uint32_t dA = sb + (uint32_t)b * (A_BYTES + B_BYTES);
    #pragma unroll
    for (int it = 0; it < 4; it++) {
        int q = tid + it * NTHR;              // 2048 chunks of 16B
        int r = q >> 3, c = q & 7;
        int cs = c ^ (r & 7);                 // SW128 swizzle
        cp16(dA + (uint32_t)(r * 128 + cs * 16),
             baseA + (size_t)r * 65536 + c * 16);
    }
    if (tid < 256)                            // B: flat 4KB
        cp16(dA + A_BYTES + (uint32_t)tid * 16,
             (const char*)g_hB + (size_t)s * 4096 + tid * 16);
    asm volatile("cp.async.commit_group;" ::: "memory");
}

// ---------------- kernel 1: h = x @ w1^T ----------------
__global__ void __launch_bounds__(256) h_kernel(const float* __restrict__ x,
                                                const float* __restrict__ w1) {
    __shared__ float sw[D_DIM * D_DIM];
    int tid = threadIdx.x;
    ((float4*)sw)[tid] = ((const float4*)w1)[tid];
    __syncthreads();

    int row = blockIdx.x * 256 + tid;
    float xr[32];
    const float4* x4 = (const float4*)(x + (size_t)row * D_DIM);
    #pragma unroll
    for (int j = 0; j < 8; j++) {
        float4 v = x4[j];
        xr[j * 4 + 0] = v.x; xr[j * 4 + 1] = v.y;
        xr[j * 4 + 2] = v.z; xr[j * 4 + 3] = v.w;
    }

    int s  = row >> 5, ks = row & 31;
    int kk = ks >> 3, r3 = ks & 7;
    int tt = r3 & 3,  p  = r3 >> 2;
    float* hb = g_hB + ((s * 8 + kk * 2 + p) * 32 + tt) * 4;
    float4* ho = (float4*)(g_h + (size_t)row * D_DIM);

    #pragma unroll
    for (int c4 = 0; c4 < 8; c4++) {
        float a[4];
        #pragma unroll
        for (int u = 0; u < 4; u++) {
            int c = c4 * 4 + u;
            float acc = 0.f;
            #pragma unroll
            for (int j = 0; j < 32; j++) acc += xr[j] * sw[c * 32 + j];
            a[u] = acc;
            int g = c & 7, nt = c >> 3;
            hb[g * 16 + nt] = __uint_as_float(f2tf32(acc));
        }
        ho[c4] = make_float4(a[0], a[1], a[2], a[3]);
    }
}

// ---------------- kernel 2: out = edges @ h + h ----------------
__global__ void __launch_bounds__(NTHR, 1)
gcn_gemm_kernel(const float* __restrict__ edges, float* __restrict__ out) {
    extern __shared__ float smem[];
    uint32_t sb = smem_u32(smem);
    const int tid = threadIdx.x, wid = tid >> 5, lane = tid & 31;
    const int g = lane >> 2, t = lane & 3;
    const int mw = wid & 7, sg = wid >> 3;     // m-warp / stage-parity group
    const int m0 = blockIdx.x * TM;

    float acc[2][4][4];                        // mt x nt x 4 (this group's partial)
    #pragma unroll
    for (int mt = 0; mt < 2; mt++)
        #pragma unroll
        for (int nt = 0; nt < 4; nt++)
            #pragma unroll
            for (int r = 0; r < 4; r++) acc[mt][nt][r] = 0.f;

    // prologue: fill all 6 stages
    for (int s = 0; s < STAGES; s++) fill_stage(edges, m0, s, s, sb, tid);

    // per-thread A fragment bases (floats): row0 = mw*32 + mt*16 + g, swizzle key = g
    const int aRow0 = (mw * 32 + g) * 32 + t;  // mt=0; mt=1 adds 16*32

    int b0 = 0;                                // slot of stage 'base'
    for (int it = 0; it < NSTAGE / QUAD; it++) {
        asm volatile("cp.async.wait_group %0;" :: "n"(STAGES - QUAD) : "memory");
        __syncthreads();

        const int base = it * QUAD;
        #pragma unroll
        for (int qq = 0; qq < 2; qq++) {
            const int q = sg + qq * 2;         // group 0: stages 0,2; group 1: 1,3
            int sl = b0 + q; if (sl >= STAGES) sl -= STAGES;
            const float* stA = smem + sl * STAGE_FLOATS;
            const float4* stB4 = (const float4*)(stA + A_FLOATS);
            #pragma unroll
            for (int kk = 0; kk < 4; kk++) {
                float4 blo = stB4[(kk * 2 + 0) * 32 + lane];
                float4 bhi = stB4[(kk * 2 + 1) * 32 + lane];
                const int c0 = ((2 * kk) ^ g) * 4;
                const int c1 = ((2 * kk + 1) ^ g) * 4;
                #pragma unroll
                for (int mt = 0; mt < 2; mt++) {
                    const int rb = aRow0 + mt * (16 * 32);
                    uint32_t a0 = f2tf32(stA[rb + c0]);
                    uint32_t a2 = f2tf32(stA[rb + c1]);
                    uint32_t a1 = f2tf32(stA[rb + 256 + c0]);   // row+8
                    uint32_t a3 = f2tf32(stA[rb + 256 + c1]);
                    mma_tf32(acc[mt][0], a0, a1, a2, a3,
                             __float_as_uint(blo.x), __float_as_uint(bhi.x));
                    mma_tf32(acc[mt][1], a0, a1, a2, a3,
                             __float_as_uint(blo.y), __float_as_uint(bhi.y));
                    mma_tf32(acc[mt][2], a0, a1, a2, a3,
                             __float_as_uint(blo.z), __float_as_uint(bhi.z));
                    mma_tf32(acc[mt][3], a0, a1, a2, a3,
                             __float_as_uint(blo.w), __float_as_uint(bhi.w));
                }
            }
        }
        __syncthreads();

        #pragma unroll
        for (int q = 0; q < QUAD; q++) {
            const int sp = base + STAGES + q;
            int sl = b0 + q; if (sl >= STAGES) sl -= STAGES;
            if (sp < NSTAGE) fill_stage(edges, m0, sp, sl, sb, tid);
            else asm volatile("cp.async.commit_group;" ::: "memory");
        }
        b0 += QUAD; if (b0 >= STAGES) b0 -= STAGES;
    }

    // ---- cross-group reduction through smem (stride-33, conflict-free) ----
    __syncthreads();
    float* red = smem;                          // 256*33 floats = 33.8KB
    if (sg == 1) {
        int rbase = (mw * 32 + lane) * 33;
        #pragma unroll
        for (int mt = 0; mt < 2; mt++)
            #pragma unroll
            for (int nt = 0; nt < 4; nt++)
                #pragma unroll
                for (int r = 0; r < 4; r++)
                    red[rbase + mt * 16 + nt * 4 + r] = acc[mt][nt][r];
    }
    __syncthreads();

    if (sg == 0) {
        int rbase = (mw * 32 + lane) * 33;
        #pragma unroll
        for (int mt = 0; mt < 2; mt++)
            #pragma unroll
            for (int nt = 0; nt < 4; nt++)
                #pragma unroll
                for (int r = 0; r < 4; r++)
                    acc[mt][nt][r] += red[rbase + mt * 16 + nt * 4 + r];

        // epilogue: out = acc + h  (D frag: rows g,g+8; cols 2t,2t+1 per n-tile)
        #pragma unroll
        for (int mt = 0; mt < 2; mt++) {
            const int row0 = m0 + mw * 32 + mt * 16 + g;
            #pragma unroll
            for (int half = 0; half < 2; half++) {
                const int row = row0 + half * 8;
                const float2* hr = (const float2*)(g_h + (size_t)row * D_DIM);
                float2* o = (float2*)(out + (size_t)row * D_DIM);
                #pragma unroll
                for (int nt = 0; nt < 4; nt++) {
                    const int c2 = nt * 4 + t;
                    float2 hv = hr[c2];
                    float2 v;
                    v.x = acc[mt][nt][half * 2 + 0] + hv.x;
                    v.y = acc[mt][nt][half * 2 + 1] + hv.y;
                    o[c2] = v;
                }
            }
        }
    }
}

// ---------------- launch ----------------
extern "C" void kernel_launch(void* const* d_in, const int* in_sizes, int n_in,
                              void* d_out, int out_size) {
    const float* x     = (const float*)d_in[0];
    const float* edges = (const float*)d_in[1];
    const float* w1    = (const float*)d_in[2];
    float* out = (float*)d_out;

    cudaFuncSetAttribute(gcn_gemm_kernel,
                         cudaFuncAttributeMaxDynamicSharedMemorySize, SMEM_TOTAL);

    h_kernel<<<N_ROWS / 256, 256>>>(x, w1);
    gcn_gemm_kernel<<<N_ROWS / TM, NTHR, SMEM_TOTAL>>>(edges, out);
}

// round 8
// speedup vs baseline: 1.8135x; 1.8135x over previous
#include <cuda_runtime.h>
#include <cstdint>

// ---------------- problem constants ----------------
#define N_ROWS 16384
#define D_DIM  32

// ---------------- GEMM tiling ----------------
#define TM      128                 // M rows per CTA
#define KB      64                  // K floats per stage (256 B per row)
#define NSTAGE  (N_ROWS / KB)       // 256
#define STAGES  5                   // smem ring buffers
#define PAIR    2                   // stages consumed per sync pair
#define NTHR    256                 // 8 warps, m=16 each

#define A_STRIDE 68                 // padded row stride in floats (bank 4g+t distinct)
#define A_FLOATS (TM * A_STRIDE)    // 8704
#define A_BYTES  (A_FLOATS * 4)     // 34816
#define B_BYTES  (KB * D_DIM * 4)   // 8192 (two 32-k fragment blocks)
#define STAGE_FLOATS (A_FLOATS + B_BYTES / 4)
#define SMEM_TOTAL (STAGES * (A_BYTES + B_BYTES))   // 215040

// scratch (device globals: no allocation allowed anywhere)
// g_hB fragment-major per 32-k block s32: float idx =
//   ((s32*8 + kk*2 + p)*32 + (g*4 + t))*4 + nt
//   holds tf32(h[k][c]), k = s32*32 + kk*8 + t + 4p, c = nt*8 + g
__device__ __align__(256) float g_hB[D_DIM * N_ROWS];
__device__ __align__(256) float g_h [N_ROWS * D_DIM];   // h[i][c], fp32 self term

// ---------------- helpers ----------------
__device__ __forceinline__ uint32_t smem_u32(const void* p) {
    uint32_t a;
    asm("{ .reg .u64 t; cvta.to.shared.u64 t, %1; cvt.u32.u64 %0, t; }"
        : "=r"(a) : "l"(p));
    return a;
}

__device__ __forceinline__ void cp16(uint32_t dst, const void* src) {
    asm volatile("cp.async.cg.shared.global [%0], [%1], 16;"
                 :: "r"(dst), "l"(src) : "memory");
}

__device__ __forceinline__ uint32_t f2tf32(float f) {
    uint32_t u;
    asm("cvt.rna.tf32.f32 %0, %1;" : "=r"(u) : "f"(f));
    return u;
}

// m16n8k8 tf32 mma: D += A*B (row-major A, col-major B, fp32 acc)
__device__ __forceinline__ void mma_tf32(float* c,
                                         uint32_t a0, uint32_t a1, uint32_t a2, uint32_t a3,
                                         uint32_t b0, uint32_t b1) {
    asm volatile(
        "mma.sync.aligned.m16n8k8.row.col.f32.tf32.tf32.f32 "
        "{%0,%1,%2,%3}, {%4,%5,%6,%7}, {%8,%9}, {%0,%1,%2,%3};"
        : "+f"(c[0]), "+f"(c[1]), "+f"(c[2]), "+f"(c[3])
        : "r"(a0), "r"(a1), "r"(a2), "r"(a3), "r"(b0), "r"(b1));
}

// fill one K-stage (A: 128 rows x 256B padded, B: 8KB flat) into ring slot b
__device__ __forceinline__ void fill_stage(const float* __restrict__ edges,
                                           int m0, int s, int b,
                                           uint32_t sb, int tid) {
    const size_t k0b = (size_t)s * (KB * 4);             // 256B per stage along K
    const char* baseA = (const char*)edges + (size_t)m0 * 65536 + k0b;
    uint32_t dA = sb + (uint32_t)b * (A_BYTES + B_BYTES);
    #pragma unroll
    for (int it = 0; it < 8; it++) {
        int q = tid + it * NTHR;              // 2048 chunks of 16B
        int r = q >> 4, c = q & 15;
        cp16(dA + (uint32_t)(r * (A_STRIDE * 4) + c * 16),
             baseA + (size_t)r * 65536 + c * 16);
    }
    // B: flat 8KB
    const char* baseB = (const char*)g_hB + (size_t)s * B_BYTES;
    uint32_t dB = dA + A_BYTES;
    cp16(dB + (uint32_t)tid * 16,                baseB + tid * 16);
    cp16(dB + (uint32_t)(tid + NTHR) * 16,       baseB + (tid + NTHR) * 16);
    asm volatile("cp.async.commit_group;" ::: "memory");
}

// ---------------- kernel 1: h = x @ w1^T ----------------
__global__ void __launch_bounds__(256) h_kernel(const float* __restrict__ x,
                                                const float* __restrict__ w1) {
    __shared__ float sw[D_DIM * D_DIM];
    int tid = threadIdx.x;
    ((float4*)sw)[tid] = ((const float4*)w1)[tid];
    __syncthreads();

    int row = blockIdx.x * 256 + tid;
    float xr[32];
    const float4* x4 = (const float4*)(x + (size_t)row * D_DIM);
    #pragma unroll
    for (int j = 0; j < 8; j++) {
        float4 v = x4[j];
        xr[j * 4 + 0] = v.x; xr[j * 4 + 1] = v.y;
        xr[j * 4 + 2] = v.z; xr[j * 4 + 3] = v.w;
    }

    int s  = row >> 5, ks = row & 31;       // s = 32-k block index
    int kk = ks >> 3, r3 = ks & 7;
    int tt = r3 & 3,  p  = r3 >> 2;
    float* hb = g_hB + ((s * 8 + kk * 2 + p) * 32 + tt) * 4;
    float4* ho = (float4*)(g_h + (size_t)row * D_DIM);

    #pragma unroll
    for (int c4 = 0; c4 < 8; c4++) {
        float a[4];
        #pragma unroll
        for (int u = 0; u < 4; u++) {
            int c = c4 * 4 + u;
            float acc = 0.f;
            #pragma unroll
            for (int j = 0; j < 32; j++) acc += xr[j] * sw[c * 32 + j];
            a[u] = acc;
            int g = c & 7, nt = c >> 3;
            hb[g * 16 + nt] = __uint_as_float(f2tf32(acc));
        }
        ho[c4] = make_float4(a[0], a[1], a[2], a[3]);
    }
}

// ---------------- kernel 2: out = edges @ h + h ----------------
__global__ void __launch_bounds__(NTHR, 1)
gcn_gemm_kernel(const float* __restrict__ edges, float* __restrict__ out) {
    extern __shared__ float smem[];
    uint32_t sb = smem_u32(smem);
    const int tid = threadIdx.x, wid = tid >> 5, lane = tid & 31;
    const int g = lane >> 2, t = lane & 3;
    const int m0 = blockIdx.x * TM;

    float acc[4][4];                          // nt x 4
    #pragma unroll
    for (int nt = 0; nt < 4; nt++)
        #pragma unroll
        for (int r = 0; r < 4; r++) acc[nt][r] = 0.f;

    // prologue: fill all 5 stages
    for (int s = 0; s < STAGES; s++) fill_stage(edges, m0, s, s, sb, tid);

    const int aBase = (wid * 16 + g) * A_STRIDE + t;

    int sl0 = 0;                              // slot of stage 'base'
    for (int it = 0; it < NSTAGE / PAIR; it++) {
        asm volatile("cp.async.wait_group %0;" :: "n"(STAGES - PAIR) : "memory");
        __syncthreads();

        const int base = it * PAIR;
        #pragma unroll
        for (int q = 0; q < PAIR; q++) {
            int sl = sl0 + q; if (sl >= STAGES) sl -= STAGES;
            const float* stA = smem + sl * STAGE_FLOATS;
            const float4* stB4 = (const float4*)(stA + A_FLOATS);
            #pragma unroll
            for (int sk = 0; sk < 2; sk++) {
                #pragma unroll
                for (int kk = 0; kk < 4; kk++) {
                    float4 blo = stB4[(sk * 8 + kk * 2 + 0) * 32 + lane];
                    float4 bhi = stB4[(sk * 8 + kk * 2 + 1) * 32 + lane];
                    const int c = sk * 32 + kk * 8;
                    uint32_t a0 = f2tf32(stA[aBase + c]);
                    uint32_t a2 = f2tf32(stA[aBase + c + 4]);
                    uint32_t a1 = f2tf32(stA[aBase + 8 * A_STRIDE + c]);
                    uint32_t a3 = f2tf32(stA[aBase + 8 * A_STRIDE + c + 4]);
                    mma_tf32(acc[0], a0, a1, a2, a3,
                             __float_as_uint(blo.x), __float_as_uint(bhi.x));
                    mma_tf32(acc[1], a0, a1, a2, a3,
                             __float_as_uint(blo.y), __float_as_uint(bhi.y));
                    mma_tf32(acc[2], a0, a1, a2, a3,
                             __float_as_uint(blo.z), __float_as_uint(bhi.z));
                    mma_tf32(acc[3], a0, a1, a2, a3,
                             __float_as_uint(blo.w), __float_as_uint(bhi.w));
                }
            }
        }
        __syncthreads();

        #pragma unroll
        for (int q = 0; q < PAIR; q++) {
            const int sp = base + STAGES + q;
            int sl = sl0 + q; if (sl >= STAGES) sl -= STAGES;
            if (sp < NSTAGE) fill_stage(edges, m0, sp, sl, sb, tid);
            else asm volatile("cp.async.commit_group;" ::: "memory");
        }
        sl0 += PAIR; if (sl0 >= STAGES) sl0 -= STAGES;
    }

    // epilogue: out = acc + h   (D frag: rows g,g+8; cols 2t,2t+1 per n-tile)
    const int row0 = m0 + wid * 16 + g;
    #pragma unroll
    for (int half = 0; half < 2; half++) {
        const int row = row0 + half * 8;
        const float2* hr = (const float2*)(g_h + (size_t)row * D_DIM);
        float2* o = (float2*)(out + (size_t)row * D_DIM);
        #pragma unroll
        for (int nt = 0; nt < 4; nt++) {
            const int c2 = nt * 4 + t;
            float2 hv = hr[c2];
            float2 v;
            v.x = acc[nt][half * 2 + 0] + hv.x;
            v.y = acc[nt][half * 2 + 1] + hv.y;
            o[c2] = v;
        }
    }
}

// ---------------- launch ----------------
extern "C" void kernel_launch(void* const* d_in, const int* in_sizes, int n_in,
                              void* d_out, int out_size) {
    const float* x     = (const float*)d_in[0];
    const float* edges = (const float*)d_in[1];
    const float* w1    = (const float*)d_in[2];
    float* out = (float*)d_out;

    cudaFuncSetAttribute(gcn_gemm_kernel,
                         cudaFuncAttributeMaxDynamicSharedMemorySize, SMEM_TOTAL);

    h_kernel<<<N_ROWS / 256, 256>>>(x, w1);
    gcn_gemm_kernel<<<N_ROWS / TM, NTHR, SMEM_TOTAL>>>(edges, out);
}